// round 1
// baseline (speedup 1.0000x reference)
#include <cuda_runtime.h>
#include <cstdint>

#define NPTS 100000
#define CCH  64

// Scratch for projected k/v (25.6 MB each). Device globals: no runtime allocation.
__device__ float g_k[NPTS * CCH];
__device__ float g_v[NPTS * CCH];

// ---- packed f32x2 helpers (ptxas won't auto-fuse; must come from PTX) ----
__device__ __forceinline__ unsigned long long pack2(float x) {
    unsigned long long r;
    asm("mov.b64 %0, {%1, %1};" : "=l"(r) : "r"(__float_as_uint(x)));
    return r;
}
__device__ __forceinline__ unsigned long long fma2(unsigned long long a,
                                                   unsigned long long b,
                                                   unsigned long long c) {
    unsigned long long d;
    asm("fma.rn.f32x2 %0, %1, %2, %3;" : "=l"(d) : "l"(a), "l"(b), "l"(c));
    return d;
}

// ============================================================================
// Kernel A: k = feats @ Wk, v = feats @ Wv      (q is fused into kernel B)
// Block: 256 threads, tile of 32 points. Thread = (point, channel-pair).
// ============================================================================
__global__ void __launch_bounds__(256) proj_kv_kernel(
    const float* __restrict__ feats,
    const float* __restrict__ Wk,
    const float* __restrict__ Wv)
{
    __shared__ __align__(16) float wk_s[64 * 64];
    __shared__ __align__(16) float wv_s[64 * 64];
    __shared__ float f_s[32][64];

    const int tid = threadIdx.x;
    for (int i = tid; i < 4096; i += 256) { wk_s[i] = Wk[i]; wv_s[i] = Wv[i]; }

    const int c2 = tid & 31;   // channel pair -> channels 2*c2, 2*c2+1
    const int pb = tid >> 5;   // warp id -> point within pass

    const int tiles = NPTS / 32;   // 100000 / 32 = 3125 exactly
    for (int t = blockIdx.x; t < tiles; t += gridDim.x) {
        const int base = t * 32;
        __syncthreads();
        // load feats tile (32 x 64), coalesced
        for (int i = tid; i < 2048; i += 256) {
            int p = i >> 6, c = i & 63;
            f_s[p][c] = feats[(base + p) * 64 + c];
        }
        __syncthreads();

        #pragma unroll
        for (int pass = 0; pass < 4; ++pass) {
            const int p = pb + pass * 8;
            const int n = base + p;
            unsigned long long ak = 0ull, av = 0ull;
            #pragma unroll
            for (int i = 0; i < 64; ++i) {
                unsigned long long ff = pack2(f_s[p][i]);   // broadcast LDS
                ak = fma2(ff, *(const unsigned long long*)&wk_s[i * 64 + 2 * c2], ak);
                av = fma2(ff, *(const unsigned long long*)&wv_s[i * 64 + 2 * c2], av);
            }
            *(unsigned long long*)&g_k[n * 64 + 2 * c2] = ak;   // coalesced STG.64
            *(unsigned long long*)&g_v[n * 64 + 2 * c2] = av;
        }
    }
}

// ============================================================================
// Kernel B: per-point attention, one warp per point.
//   - q = feats[n] @ Wq (lane = channel pair)
//   - scores: lane = (neighbor j = l>>1, half = l&1) -> 4 heads each,
//     coalesced 128B k-row halves, softmax via xor-shuffles {2,4,8,16}
//   - v stage: all lanes stream each neighbor row (coalesced float2)
//   - out = o @ Wo + bo (lane = channel pair)
// ============================================================================
__global__ void __launch_bounds__(256) attn_kernel(
    const float* __restrict__ feats,
    const int*   __restrict__ knn,
    const float* __restrict__ Wq,
    const float* __restrict__ Wo,
    const float* __restrict__ bo,
    float*       __restrict__ out)
{
    __shared__ __align__(16) float wq_s[64 * 64];
    __shared__ __align__(16) float wo_s[64 * 64];
    __shared__ __align__(16) float bo_s[64];
    __shared__ __align__(16) float f_s[8][64];
    __shared__ __align__(16) float q_s[8][64];
    __shared__ __align__(16) float attn_s[8][128];   // [j][head]
    __shared__ __align__(16) float o_s[8][64];
    __shared__ int idx_s[8][16];

    const int tid = threadIdx.x;
    for (int i = tid; i < 4096; i += 256) { wq_s[i] = Wq[i]; wo_s[i] = Wo[i]; }
    if (tid < 64) bo_s[tid] = bo[tid];
    __syncthreads();

    const int w = tid >> 5;
    const int l = tid & 31;
    const int j = l >> 1;      // neighbor 0..15
    const int half = l & 1;    // which 32-channel half of the row
    const float inv_sqrt_d = 0.3535533905932738f;   // 1/sqrt(8)

    const int warp_id = blockIdx.x * 8 + w;
    const int nwarps  = gridDim.x * 8;

    for (int n = warp_id; n < NPTS; n += nwarps) {
        __syncwarp();
        // ---- load feats row + knn indices ----
        *(float2*)&f_s[w][2 * l] = *(const float2*)&feats[n * 64 + 2 * l];
        const int idx = knn[n * 16 + j];
        if (half == 0) idx_s[w][j] = idx;
        __syncwarp();

        // ---- q projection: channels 2l, 2l+1 ----
        unsigned long long q2 = 0ull;
        #pragma unroll
        for (int i = 0; i < 64; ++i) {
            unsigned long long ff = pack2(f_s[w][i]);
            q2 = fma2(ff, *(const unsigned long long*)&wq_s[i * 64 + 2 * l], q2);
        }
        *(unsigned long long*)&q_s[w][2 * l] = q2;
        __syncwarp();

        // ---- scores for neighbor j, heads half*4 .. half*4+3 ----
        float kr[32];
        const float* krow = &g_k[idx * 64 + half * 32];
        #pragma unroll
        for (int t4 = 0; t4 < 8; ++t4)
            *(float4*)&kr[t4 * 4] = *(const float4*)&krow[t4 * 4];

        const float* qh = &q_s[w][half * 32];
        float s[4];
        #pragma unroll
        for (int hh = 0; hh < 4; ++hh) {
            float acc = 0.f;
            #pragma unroll
            for (int d = 0; d < 8; ++d)
                acc = fmaf(qh[hh * 8 + d], kr[hh * 8 + d], acc);
            s[hh] = acc * inv_sqrt_d;
        }

        // ---- softmax over the 16 neighbors (lanes with same `half`) ----
        #pragma unroll
        for (int hh = 0; hh < 4; ++hh) {
            float m = s[hh];
            m = fmaxf(m, __shfl_xor_sync(0xffffffffu, m, 2));
            m = fmaxf(m, __shfl_xor_sync(0xffffffffu, m, 4));
            m = fmaxf(m, __shfl_xor_sync(0xffffffffu, m, 8));
            m = fmaxf(m, __shfl_xor_sync(0xffffffffu, m, 16));
            float e = exp2f((s[hh] - m) * 1.4426950408889634f);
            float sm = e;
            sm += __shfl_xor_sync(0xffffffffu, sm, 2);
            sm += __shfl_xor_sync(0xffffffffu, sm, 4);
            sm += __shfl_xor_sync(0xffffffffu, sm, 8);
            sm += __shfl_xor_sync(0xffffffffu, sm, 16);
            attn_s[w][j * 8 + half * 4 + hh] = __fdividef(e, sm);
        }
        __syncwarp();

        // ---- attended value: lane owns channels 2l, 2l+1 (head = l>>2) ----
        unsigned long long o2 = 0ull;
        #pragma unroll
        for (int jj = 0; jj < 16; ++jj) {
            const int ij = idx_s[w][jj];
            const float a = attn_s[w][jj * 8 + (l >> 2)];
            unsigned long long v2 =
                *(const unsigned long long*)&g_v[ij * 64 + 2 * l];  // coalesced
            o2 = fma2(pack2(a), v2, o2);
        }
        *(unsigned long long*)&o_s[w][2 * l] = o2;
        __syncwarp();

        // ---- output projection + bias ----
        unsigned long long r2 = *(const unsigned long long*)&bo_s[2 * l];
        #pragma unroll
        for (int i = 0; i < 64; ++i) {
            unsigned long long oo = pack2(o_s[w][i]);
            r2 = fma2(oo, *(const unsigned long long*)&wo_s[i * 64 + 2 * l], r2);
        }
        *(unsigned long long*)&out[n * 64 + 2 * l] = r2;   // coalesced STG.64
    }
}

// ============================================================================
extern "C" void kernel_launch(void* const* d_in, const int* in_sizes, int n_in,
                              void* d_out, int out_size) {
    const float* feats = (const float*)d_in[0];
    const int*   knn   = (const int*)  d_in[1];
    const float* Wq    = (const float*)d_in[2];
    const float* Wk    = (const float*)d_in[3];
    const float* Wv    = (const float*)d_in[4];
    const float* Wo    = (const float*)d_in[5];
    const float* bo    = (const float*)d_in[6];
    float* out = (float*)d_out;

    proj_kv_kernel<<<444, 256>>>(feats, Wk, Wv);
    attn_kernel<<<740, 256>>>(feats, knn, Wq, Wo, bo, out);
}

// round 2
// speedup vs baseline: 1.4909x; 1.4909x over previous
#include <cuda_runtime.h>
#include <cstdint>

#define NPTS 100000
typedef unsigned long long ull;

// Scratch (device globals: allocation-guard safe). 4 x 25.6 MB.
__device__ float g_q[NPTS * 64];
__device__ float g_k[NPTS * 64];
__device__ float g_v[NPTS * 64];
__device__ float g_o[NPTS * 64];

// ---- packed f32x2 helpers ----
__device__ __forceinline__ ull pack2(float x) {
    ull r;
    asm("mov.b64 %0, {%1, %1};" : "=l"(r) : "r"(__float_as_uint(x)));
    return r;
}
__device__ __forceinline__ ull fma2(ull a, ull b, ull c) {
    ull d;
    asm("fma.rn.f32x2 %0, %1, %2, %3;" : "=l"(d) : "l"(a), "l"(b), "l"(c));
    return d;
}

// ============================================================================
// Kernel 1: q,k,v = feats @ {Wq,Wk,Wv}. Register-tiled GEMM.
// Block = 256 thr, tile = 64 points. Thread = (channel pair c2, point row pr),
// accumulates 8 points x 2 channels x 3 matrices in registers.
// ============================================================================
__global__ void __launch_bounds__(256) proj_qkv_kernel(
    const float* __restrict__ feats,
    const float* __restrict__ Wq,
    const float* __restrict__ Wk,
    const float* __restrict__ Wv)
{
    __shared__ __align__(16) float wq_s[4096];
    __shared__ __align__(16) float wk_s[4096];
    __shared__ __align__(16) float wv_s[4096];
    __shared__ __align__(16) float f_s[64][64];

    const int tid = threadIdx.x;
    for (int i = tid; i < 4096; i += 256) {
        wq_s[i] = Wq[i]; wk_s[i] = Wk[i]; wv_s[i] = Wv[i];
    }
    const int base = blockIdx.x * 64;
    for (int i = tid; i < 4096; i += 256) {
        int p = i >> 6, c = i & 63, n = base + p;
        f_s[p][c] = (n < NPTS) ? feats[n * 64 + c] : 0.f;
    }
    __syncthreads();

    const int c2 = tid & 31;       // channels 2*c2, 2*c2+1
    const int pr = tid >> 5;       // point row 0..7

    ull aq[8], ak[8], av[8];
    #pragma unroll
    for (int pp = 0; pp < 8; ++pp) { aq[pp] = 0ull; ak[pp] = 0ull; av[pp] = 0ull; }

    #pragma unroll
    for (int i = 0; i < 64; i += 2) {
        const ull wq0 = *(const ull*)&wq_s[i * 64 + 2 * c2];
        const ull wq1 = *(const ull*)&wq_s[(i + 1) * 64 + 2 * c2];
        const ull wk0 = *(const ull*)&wk_s[i * 64 + 2 * c2];
        const ull wk1 = *(const ull*)&wk_s[(i + 1) * 64 + 2 * c2];
        const ull wv0 = *(const ull*)&wv_s[i * 64 + 2 * c2];
        const ull wv1 = *(const ull*)&wv_s[(i + 1) * 64 + 2 * c2];
        #pragma unroll
        for (int pp = 0; pp < 8; ++pp) {
            const float2 f2 = *(const float2*)&f_s[pr + 8 * pp][i];  // broadcast LDS.64
            const ull f0 = pack2(f2.x), f1 = pack2(f2.y);
            aq[pp] = fma2(f0, wq0, aq[pp]); aq[pp] = fma2(f1, wq1, aq[pp]);
            ak[pp] = fma2(f0, wk0, ak[pp]); ak[pp] = fma2(f1, wk1, ak[pp]);
            av[pp] = fma2(f0, wv0, av[pp]); av[pp] = fma2(f1, wv1, av[pp]);
        }
    }
    #pragma unroll
    for (int pp = 0; pp < 8; ++pp) {
        const int n = base + pr + 8 * pp;
        if (n < NPTS) {
            *(ull*)&g_q[n * 64 + 2 * c2] = aq[pp];
            *(ull*)&g_k[n * 64 + 2 * c2] = ak[pp];
            *(ull*)&g_v[n * 64 + 2 * c2] = av[pp];
        }
    }
}

// ============================================================================
// Kernel 2: attention gather + softmax + value mix. One warp per point.
// Every k/v row is loaded fully coalesced by the whole warp (lane l owns
// channels 2l,2l+1; its head = l>>2 matches the attn weight it needs).
// ============================================================================
__global__ void __launch_bounds__(256) attn_kernel(const int* __restrict__ knn)
{
    const int w = threadIdx.x >> 5;
    const int l = threadIdx.x & 31;
    const int n = blockIdx.x * 8 + w;
    if (n >= NPTS) return;

    const float2 q2 = *(const float2*)&g_q[n * 64 + 2 * l];

    int idxv = 0;
    if (l < 16) idxv = knn[n * 16 + l];

    int idxs[16];
    #pragma unroll
    for (int j = 0; j < 16; ++j)
        idxs[j] = __shfl_sync(0xffffffffu, idxv, j);

    // prefetch all 16 k rows (coalesced, MLP=16)
    float2 k2v[16];
    #pragma unroll
    for (int j = 0; j < 16; ++j)
        k2v[j] = *(const float2*)&g_k[idxs[j] * 64 + 2 * l];

    float a[16];
    #pragma unroll
    for (int j = 0; j < 16; ++j) {
        float p = q2.x * k2v[j].x + q2.y * k2v[j].y;
        p += __shfl_xor_sync(0xffffffffu, p, 1);
        p += __shfl_xor_sync(0xffffffffu, p, 2);   // 4-lane group = one head
        a[j] = p * 0.3535533905932738f;            // * 1/sqrt(8)
    }

    // softmax over 16 neighbors, fully in registers (redundant per lane)
    float m = a[0];
    #pragma unroll
    for (int j = 1; j < 16; ++j) m = fmaxf(m, a[j]);
    float s = 0.f;
    #pragma unroll
    for (int j = 0; j < 16; ++j) {
        a[j] = exp2f((a[j] - m) * 1.4426950408889634f);
        s += a[j];
    }
    const float inv = __fdividef(1.f, s);

    float2 o2 = make_float2(0.f, 0.f);
    #pragma unroll
    for (int j = 0; j < 16; ++j) {
        const float2 v2 = *(const float2*)&g_v[idxs[j] * 64 + 2 * l];
        const float aj = a[j] * inv;
        o2.x = fmaf(aj, v2.x, o2.x);
        o2.y = fmaf(aj, v2.y, o2.y);
    }
    *(float2*)&g_o[n * 64 + 2 * l] = o2;
}

// ============================================================================
// Kernel 3: out = g_o @ Wo + bo. Register-tiled GEMM, tile 64 points.
// ============================================================================
__global__ void __launch_bounds__(256) out_proj_kernel(
    const float* __restrict__ Wo,
    const float* __restrict__ bo,
    float* __restrict__ out)
{
    __shared__ __align__(16) float wo_s[4096];
    __shared__ __align__(16) float f_s[64][64];

    const int tid = threadIdx.x;
    for (int i = tid; i < 4096; i += 256) wo_s[i] = Wo[i];
    const int base = blockIdx.x * 64;
    for (int i = tid; i < 4096; i += 256) {
        int p = i >> 6, c = i & 63, n = base + p;
        f_s[p][c] = (n < NPTS) ? g_o[n * 64 + c] : 0.f;
    }
    __syncthreads();

    const int c2 = tid & 31;
    const int pr = tid >> 5;
    const float2 b2 = *(const float2*)&bo[2 * c2];
    ull bias;
    asm("mov.b64 %0, {%1, %2};" : "=l"(bias)
        : "r"(__float_as_uint(b2.x)), "r"(__float_as_uint(b2.y)));

    ull acc[8];
    #pragma unroll
    for (int pp = 0; pp < 8; ++pp) acc[pp] = bias;

    #pragma unroll
    for (int i = 0; i < 64; i += 2) {
        const ull w0 = *(const ull*)&wo_s[i * 64 + 2 * c2];
        const ull w1 = *(const ull*)&wo_s[(i + 1) * 64 + 2 * c2];
        #pragma unroll
        for (int pp = 0; pp < 8; ++pp) {
            const float2 f2 = *(const float2*)&f_s[pr + 8 * pp][i];
            acc[pp] = fma2(pack2(f2.x), w0, acc[pp]);
            acc[pp] = fma2(pack2(f2.y), w1, acc[pp]);
        }
    }
    #pragma unroll
    for (int pp = 0; pp < 8; ++pp) {
        const int n = base + pr + 8 * pp;
        if (n < NPTS) *(ull*)&out[n * 64 + 2 * c2] = acc[pp];
    }
}

// ============================================================================
extern "C" void kernel_launch(void* const* d_in, const int* in_sizes, int n_in,
                              void* d_out, int out_size) {
    const float* feats = (const float*)d_in[0];
    const int*   knn   = (const int*)  d_in[1];
    const float* Wq    = (const float*)d_in[2];
    const float* Wk    = (const float*)d_in[3];
    const float* Wv    = (const float*)d_in[4];
    const float* Wo    = (const float*)d_in[5];
    const float* bo    = (const float*)d_in[6];
    float* out = (float*)d_out;

    proj_qkv_kernel<<<1563, 256>>>(feats, Wq, Wk, Wv);
    attn_kernel<<<12500, 256>>>(knn);
    out_proj_kernel<<<1563, 256>>>(Wo, bo, out);
}

// round 5
// speedup vs baseline: 1.7490x; 1.1731x over previous
#include <cuda_runtime.h>
#include <cuda_fp16.h>
#include <cstdint>

#define NPTS 100000
typedef unsigned long long ull;

// Scratch (device globals). q,o fp32; k,v fp16 (halves attn gather bytes).
__device__ float  g_q[NPTS * 64];
__device__ __half g_k[NPTS * 64];
__device__ __half g_v[NPTS * 64];
__device__ float  g_o[NPTS * 64];

// ---- packed f32x2 helpers ----
__device__ __forceinline__ ull pack2(float x) {
    ull r;
    asm("mov.b64 %0, {%1, %1};" : "=l"(r) : "r"(__float_as_uint(x)));
    return r;
}
__device__ __forceinline__ ull packxy(float x, float y) {
    ull r;
    asm("mov.b64 %0, {%1, %2};" : "=l"(r) : "f"(x), "f"(y));
    return r;
}
__device__ __forceinline__ float2 unpack2(ull a) {
    float2 f;
    asm("mov.b64 {%0, %1}, %2;" : "=f"(f.x), "=f"(f.y) : "l"(a));
    return f;
}
__device__ __forceinline__ ull fma2(ull a, ull b, ull c) {
    ull d;
    asm("fma.rn.f32x2 %0, %1, %2, %3;" : "=l"(d) : "l"(a), "l"(b), "l"(c));
    return d;
}

// ============================================================================
// Kernel 1: q,k,v = feats @ {Wq,Wk,Wv}.
// Tile 64 points. Thread = (4 channels, 4 points). Feats stored in SMEM
// pre-duplicated ({f,f} 8B) so one LDS.64 feeds FFMA2 with no MOVs.
// Per i: 10 LDS + 24 fully-independent FFMA2.
// ============================================================================
__global__ void __launch_bounds__(256) proj_qkv_kernel(
    const float* __restrict__ feats,
    const float* __restrict__ Wq,
    const float* __restrict__ Wk,
    const float* __restrict__ Wv)
{
    __shared__ __align__(16) float wq_s[4096];
    __shared__ __align__(16) float wk_s[4096];
    __shared__ __align__(16) float wv_s[4096];
    __shared__ __align__(16) ull   fdup[64][64];   // 32 KB

    const int tid = threadIdx.x;
    const int base = blockIdx.x * 64;
    for (int i = tid; i < 4096; i += 256) {
        wq_s[i] = Wq[i]; wk_s[i] = Wk[i]; wv_s[i] = Wv[i];
        int p = i >> 6, c = i & 63, n = base + p;
        fdup[p][c] = pack2((n < NPTS) ? feats[n * 64 + c] : 0.f);
    }
    __syncthreads();

    const int c4 = tid & 15;    // channels 4*c4 .. 4*c4+3
    const int pr = tid >> 4;    // points pr, pr+16, pr+32, pr+48

    ull aq[4][2], ak[4][2], av[4][2];
    #pragma unroll
    for (int pp = 0; pp < 4; ++pp)
        #pragma unroll
        for (int h = 0; h < 2; ++h) { aq[pp][h] = 0; ak[pp][h] = 0; av[pp][h] = 0; }

    #pragma unroll
    for (int i = 0; i < 64; ++i) {
        const ull wq0 = *(const ull*)&wq_s[i * 64 + 4 * c4];
        const ull wq1 = *(const ull*)&wq_s[i * 64 + 4 * c4 + 2];
        const ull wk0 = *(const ull*)&wk_s[i * 64 + 4 * c4];
        const ull wk1 = *(const ull*)&wk_s[i * 64 + 4 * c4 + 2];
        const ull wv0 = *(const ull*)&wv_s[i * 64 + 4 * c4];
        const ull wv1 = *(const ull*)&wv_s[i * 64 + 4 * c4 + 2];
        #pragma unroll
        for (int pp = 0; pp < 4; ++pp) {
            const ull f = fdup[pr + 16 * pp][i];    // broadcast LDS.64, pre-packed
            aq[pp][0] = fma2(f, wq0, aq[pp][0]);
            aq[pp][1] = fma2(f, wq1, aq[pp][1]);
            ak[pp][0] = fma2(f, wk0, ak[pp][0]);
            ak[pp][1] = fma2(f, wk1, ak[pp][1]);
            av[pp][0] = fma2(f, wv0, av[pp][0]);
            av[pp][1] = fma2(f, wv1, av[pp][1]);
        }
    }

    #pragma unroll
    for (int pp = 0; pp < 4; ++pp) {
        const int n = base + pr + 16 * pp;
        if (n < NPTS) {
            *(ull*)&g_q[n * 64 + 4 * c4]     = aq[pp][0];
            *(ull*)&g_q[n * 64 + 4 * c4 + 2] = aq[pp][1];
            const float2 k0 = unpack2(ak[pp][0]), k1 = unpack2(ak[pp][1]);
            const float2 v0 = unpack2(av[pp][0]), v1 = unpack2(av[pp][1]);
            *(__half2*)&g_k[n * 64 + 4 * c4]     = __floats2half2_rn(k0.x, k0.y);
            *(__half2*)&g_k[n * 64 + 4 * c4 + 2] = __floats2half2_rn(k1.x, k1.y);
            *(__half2*)&g_v[n * 64 + 4 * c4]     = __floats2half2_rn(v0.x, v0.y);
            *(__half2*)&g_v[n * 64 + 4 * c4 + 2] = __floats2half2_rn(v1.x, v1.y);
        }
    }
}

// ============================================================================
// Kernel 2: attention gather + softmax + value mix. One warp per point.
// k/v rows are fp16 (128B per row, fully coalesced: lane l -> half2 @ 2l).
// ============================================================================
__global__ void __launch_bounds__(256) attn_kernel(const int* __restrict__ knn)
{
    const int w = threadIdx.x >> 5;
    const int l = threadIdx.x & 31;
    const int n = blockIdx.x * 8 + w;
    if (n >= NPTS) return;

    const float2 q2 = *(const float2*)&g_q[n * 64 + 2 * l];

    int idxv = 0;
    if (l < 16) idxv = knn[n * 16 + l];
    int idxs[16];
    #pragma unroll
    for (int j = 0; j < 16; ++j)
        idxs[j] = __shfl_sync(0xffffffffu, idxv, j);

    // prefetch all 16 k rows (coalesced half2, MLP=16)
    __half2 kh[16];
    #pragma unroll
    for (int j = 0; j < 16; ++j)
        kh[j] = *(const __half2*)&g_k[idxs[j] * 64 + 2 * l];

    float a[16];
    #pragma unroll
    for (int j = 0; j < 16; ++j) {
        const float2 kf = __half22float2(kh[j]);
        float p = q2.x * kf.x + q2.y * kf.y;
        p += __shfl_xor_sync(0xffffffffu, p, 1);
        p += __shfl_xor_sync(0xffffffffu, p, 2);   // 4-lane group = one head
        a[j] = p * 0.3535533905932738f;            // * 1/sqrt(8)
    }

    float m = a[0];
    #pragma unroll
    for (int j = 1; j < 16; ++j) m = fmaxf(m, a[j]);
    float s = 0.f;
    #pragma unroll
    for (int j = 0; j < 16; ++j) {
        a[j] = exp2f((a[j] - m) * 1.4426950408889634f);
        s += a[j];
    }
    const float inv = __fdividef(1.f, s);

    float2 o2 = make_float2(0.f, 0.f);
    #pragma unroll
    for (int j = 0; j < 16; ++j) {
        const float2 vf = __half22float2(*(const __half2*)&g_v[idxs[j] * 64 + 2 * l]);
        const float aj = a[j] * inv;
        o2.x = fmaf(aj, vf.x, o2.x);
        o2.y = fmaf(aj, vf.y, o2.y);
    }
    *(float2*)&g_o[n * 64 + 2 * l] = o2;
}

// ============================================================================
// Kernel 3: out = g_o @ Wo + bo. Same dup-feats / 4ch x 4pt structure.
// Per i: 6 LDS + 8 FFMA2.
// ============================================================================
__global__ void __launch_bounds__(256) out_proj_kernel(
    const float* __restrict__ Wo,
    const float* __restrict__ bo,
    float* __restrict__ out)
{
    __shared__ __align__(16) float wo_s[4096];
    __shared__ __align__(16) ull   fdup[64][64];

    const int tid = threadIdx.x;
    const int base = blockIdx.x * 64;
    for (int i = tid; i < 4096; i += 256) {
        wo_s[i] = Wo[i];
        int p = i >> 6, c = i & 63, n = base + p;
        fdup[p][c] = pack2((n < NPTS) ? g_o[n * 64 + c] : 0.f);
    }
    __syncthreads();

    const int c4 = tid & 15;
    const int pr = tid >> 4;

    const float2 b0 = *(const float2*)&bo[4 * c4];
    const float2 b1 = *(const float2*)&bo[4 * c4 + 2];
    ull acc[4][2];
    #pragma unroll
    for (int pp = 0; pp < 4; ++pp) {
        acc[pp][0] = packxy(b0.x, b0.y);
        acc[pp][1] = packxy(b1.x, b1.y);
    }

    #pragma unroll
    for (int i = 0; i < 64; ++i) {
        const ull w0 = *(const ull*)&wo_s[i * 64 + 4 * c4];
        const ull w1 = *(const ull*)&wo_s[i * 64 + 4 * c4 + 2];
        #pragma unroll
        for (int pp = 0; pp < 4; ++pp) {
            const ull f = fdup[pr + 16 * pp][i];
            acc[pp][0] = fma2(f, w0, acc[pp][0]);
            acc[pp][1] = fma2(f, w1, acc[pp][1]);
        }
    }

    #pragma unroll
    for (int pp = 0; pp < 4; ++pp) {
        const int n = base + pr + 16 * pp;
        if (n < NPTS) {
            *(ull*)&out[n * 64 + 4 * c4]     = acc[pp][0];
            *(ull*)&out[n * 64 + 4 * c4 + 2] = acc[pp][1];
        }
    }
}

// ============================================================================
extern "C" void kernel_launch(void* const* d_in, const int* in_sizes, int n_in,
                              void* d_out, int out_size) {
    const float* feats = (const float*)d_in[0];
    const int*   knn   = (const int*)  d_in[1];
    const float* Wq    = (const float*)d_in[2];
    const float* Wk    = (const float*)d_in[3];
    const float* Wv    = (const float*)d_in[4];
    const float* Wo    = (const float*)d_in[5];
    const float* bo    = (const float*)d_in[6];
    float* out = (float*)d_out;

    proj_qkv_kernel<<<1563, 256>>>(feats, Wq, Wk, Wv);
    attn_kernel<<<12500, 256>>>(knn);
    out_proj_kernel<<<1563, 256>>>(Wo, bo, out);
}

// round 9
// speedup vs baseline: 2.1642x; 1.2375x over previous
#include <cuda_runtime.h>
#include <cuda_fp16.h>
#include <cstdint>

#define NPTS 100000
#define NTILES 1563            // ceil(100000/64)
typedef unsigned long long ull;

// Scratch (device globals). q,o fp32; k,v fp16 (halves attn gather bytes).
__device__ float  g_q[NPTS * 64];
__device__ __half g_k[NPTS * 64];
__device__ __half g_v[NPTS * 64];
__device__ float  g_o[NPTS * 64];

// ---- packed f32x2 helpers ----
__device__ __forceinline__ ull pack2(float x) {
    ull r;
    asm("mov.b64 %0, {%1, %1};" : "=l"(r) : "r"(__float_as_uint(x)));
    return r;
}
__device__ __forceinline__ ull packxy(float x, float y) {
    ull r;
    asm("mov.b64 %0, {%1, %2};" : "=l"(r) : "f"(x), "f"(y));
    return r;
}
__device__ __forceinline__ float2 unpack2(ull a) {
    float2 f;
    asm("mov.b64 {%0, %1}, %2;" : "=f"(f.x), "=f"(f.y) : "l"(a));
    return f;
}
__device__ __forceinline__ ull fma2(ull a, ull b, ull c) {
    ull d;
    asm("fma.rn.f32x2 %0, %1, %2, %3;" : "=l"(d) : "l"(a), "l"(b), "l"(c));
    return d;
}

// load one 64-point feats tile into 4 float4 regs per thread (coalesced LDG.128)
__device__ __forceinline__ void load_tile(const float* __restrict__ src,
                                          int base, float4* buf) {
    #pragma unroll
    for (int k2 = 0; k2 < 4; ++k2) {
        const int fi = (threadIdx.x + k2 * 256) * 4;   // float index in tile
        const int n = base + (fi >> 6);
        buf[k2] = (n < NPTS) ? *(const float4*)&src[(size_t)base * 64 + fi]
                             : make_float4(0.f, 0.f, 0.f, 0.f);
    }
}

// store the 4 float4 regs into fdup as duplicated {f,f} pairs (STS.128 x2 each)
__device__ __forceinline__ void store_tile_dup(ull (*fdup)[64], const float4* buf) {
    #pragma unroll
    for (int k2 = 0; k2 < 4; ++k2) {
        const int fi = (threadIdx.x + k2 * 256) * 4;
        const int p = fi >> 6, c = fi & 63;
        ulonglong2 a, b;
        a.x = pack2(buf[k2].x); a.y = pack2(buf[k2].y);
        b.x = pack2(buf[k2].z); b.y = pack2(buf[k2].w);
        *(ulonglong2*)&fdup[p][c]     = a;
        *(ulonglong2*)&fdup[p][c + 2] = b;
    }
}

// ============================================================================
// Kernel 1: q,k,v = feats @ {Wq,Wk,Wv}. PERSISTENT: weights loaded once per
// block; loop over tiles with register-prefetched feats (LDG hidden by FFMA2).
// Thread = (4 channels, 4 points). Per i-step: 3 LDS.128 + 4 LDS.64 + 24 FFMA2.
// ============================================================================
__global__ void __launch_bounds__(256) proj_qkv_kernel(
    const float* __restrict__ feats,
    const float* __restrict__ Wq,
    const float* __restrict__ Wk,
    const float* __restrict__ Wv)
{
    __shared__ __align__(16) float wq_s[4096];
    __shared__ __align__(16) float wk_s[4096];
    __shared__ __align__(16) float wv_s[4096];
    __shared__ __align__(16) ull   fdup[64][64];   // 32 KB

    const int tid = threadIdx.x;
    for (int i = tid; i < 4096; i += 256) {
        wq_s[i] = Wq[i]; wk_s[i] = Wk[i]; wv_s[i] = Wv[i];
    }

    const int c4 = tid & 15;    // channels 4*c4 .. 4*c4+3
    const int pr = tid >> 4;    // points pr, pr+16, pr+32, pr+48

    float4 buf[4];
    int t = blockIdx.x;
    if (t < NTILES) load_tile(feats, t * 64, buf);

    for (; t < NTILES; t += gridDim.x) {
        const int base = t * 64;
        store_tile_dup(fdup, buf);
        __syncthreads();                       // fdup (and, first iter, weights) ready

        const int tn = t + gridDim.x;
        if (tn < NTILES) load_tile(feats, tn * 64, buf);   // prefetch next tile

        ull aq[4][2], ak[4][2], av[4][2];
        #pragma unroll
        for (int pp = 0; pp < 4; ++pp)
            #pragma unroll
            for (int h = 0; h < 2; ++h) { aq[pp][h] = 0; ak[pp][h] = 0; av[pp][h] = 0; }

        #pragma unroll
        for (int i = 0; i < 64; ++i) {
            const ulonglong2 wq01 = *(const ulonglong2*)&wq_s[i * 64 + 4 * c4];
            const ulonglong2 wk01 = *(const ulonglong2*)&wk_s[i * 64 + 4 * c4];
            const ulonglong2 wv01 = *(const ulonglong2*)&wv_s[i * 64 + 4 * c4];
            #pragma unroll
            for (int pp = 0; pp < 4; ++pp) {
                const ull f = fdup[pr + 16 * pp][i];    // broadcast LDS.64
                aq[pp][0] = fma2(f, wq01.x, aq[pp][0]);
                aq[pp][1] = fma2(f, wq01.y, aq[pp][1]);
                ak[pp][0] = fma2(f, wk01.x, ak[pp][0]);
                ak[pp][1] = fma2(f, wk01.y, ak[pp][1]);
                av[pp][0] = fma2(f, wv01.x, av[pp][0]);
                av[pp][1] = fma2(f, wv01.y, av[pp][1]);
            }
        }

        #pragma unroll
        for (int pp = 0; pp < 4; ++pp) {
            const int n = base + pr + 16 * pp;
            if (n < NPTS) {
                *(ull*)&g_q[n * 64 + 4 * c4]     = aq[pp][0];
                *(ull*)&g_q[n * 64 + 4 * c4 + 2] = aq[pp][1];
                const float2 k0 = unpack2(ak[pp][0]), k1 = unpack2(ak[pp][1]);
                const float2 v0 = unpack2(av[pp][0]), v1 = unpack2(av[pp][1]);
                *(__half2*)&g_k[n * 64 + 4 * c4]     = __floats2half2_rn(k0.x, k0.y);
                *(__half2*)&g_k[n * 64 + 4 * c4 + 2] = __floats2half2_rn(k1.x, k1.y);
                *(__half2*)&g_v[n * 64 + 4 * c4]     = __floats2half2_rn(v0.x, v0.y);
                *(__half2*)&g_v[n * 64 + 4 * c4 + 2] = __floats2half2_rn(v1.x, v1.y);
            }
        }
        __syncthreads();                       // all reads of fdup done
    }
}

// ============================================================================
// Kernel 2: attention gather + softmax + value mix. One warp per point.
// k AND v rows prefetched up front (32 outstanding coalesced LDG.64/lane).
// ============================================================================
__global__ void __launch_bounds__(256) attn_kernel(const int* __restrict__ knn)
{
    const int w = threadIdx.x >> 5;
    const int l = threadIdx.x & 31;
    const int n = blockIdx.x * 8 + w;
    if (n >= NPTS) return;

    int idxv = 0;
    if (l < 16) idxv = knn[n * 16 + l];
    int idxs[16];
    #pragma unroll
    for (int j = 0; j < 16; ++j)
        idxs[j] = __shfl_sync(0xffffffffu, idxv, j);

    const float2 q2 = *(const float2*)&g_q[n * 64 + 2 * l];

    // prefetch all 16 k rows AND 16 v rows (coalesced half2, MLP=32)
    __half2 kh[16], vh[16];
    #pragma unroll
    for (int j = 0; j < 16; ++j) {
        kh[j] = *(const __half2*)&g_k[idxs[j] * 64 + 2 * l];
        vh[j] = *(const __half2*)&g_v[idxs[j] * 64 + 2 * l];
    }

    float a[16];
    #pragma unroll
    for (int j = 0; j < 16; ++j) {
        const float2 kf = __half22float2(kh[j]);
        float p = q2.x * kf.x + q2.y * kf.y;
        p += __shfl_xor_sync(0xffffffffu, p, 1);
        p += __shfl_xor_sync(0xffffffffu, p, 2);   // 4-lane group = one head
        a[j] = p * 0.3535533905932738f;            // * 1/sqrt(8)
    }

    float m = a[0];
    #pragma unroll
    for (int j = 1; j < 16; ++j) m = fmaxf(m, a[j]);
    float s = 0.f;
    #pragma unroll
    for (int j = 0; j < 16; ++j) {
        a[j] = exp2f((a[j] - m) * 1.4426950408889634f);
        s += a[j];
    }
    const float inv = __fdividef(1.f, s);

    float2 o2 = make_float2(0.f, 0.f);
    #pragma unroll
    for (int j = 0; j < 16; ++j) {
        const float2 vf = __half22float2(vh[j]);
        const float aj = a[j] * inv;
        o2.x = fmaf(aj, vf.x, o2.x);
        o2.y = fmaf(aj, vf.y, o2.y);
    }
    *(float2*)&g_o[n * 64 + 2 * l] = o2;
}

// ============================================================================
// Kernel 3: out = g_o @ Wo + bo. PERSISTENT + pipelined, same structure.
// Per i-step: 1 LDS.128 + 4 LDS.64 + 8 FFMA2.
// ============================================================================
__global__ void __launch_bounds__(256) out_proj_kernel(
    const float* __restrict__ Wo,
    const float* __restrict__ bo,
    float* __restrict__ out)
{
    __shared__ __align__(16) float wo_s[4096];
    __shared__ __align__(16) ull   fdup[64][64];

    const int tid = threadIdx.x;
    for (int i = tid; i < 4096; i += 256) wo_s[i] = Wo[i];

    const int c4 = tid & 15;
    const int pr = tid >> 4;

    const float2 b0 = *(const float2*)&bo[4 * c4];
    const float2 b1 = *(const float2*)&bo[4 * c4 + 2];
    const ull bias0 = packxy(b0.x, b0.y);
    const ull bias1 = packxy(b1.x, b1.y);

    float4 buf[4];
    int t = blockIdx.x;
    if (t < NTILES) load_tile(g_o, t * 64, buf);

    for (; t < NTILES; t += gridDim.x) {
        const int base = t * 64;
        store_tile_dup(fdup, buf);
        __syncthreads();

        const int tn = t + gridDim.x;
        if (tn < NTILES) load_tile(g_o, tn * 64, buf);

        ull acc[4][2];
        #pragma unroll
        for (int pp = 0; pp < 4; ++pp) { acc[pp][0] = bias0; acc[pp][1] = bias1; }

        #pragma unroll
        for (int i = 0; i < 64; ++i) {
            const ulonglong2 w01 = *(const ulonglong2*)&wo_s[i * 64 + 4 * c4];
            #pragma unroll
            for (int pp = 0; pp < 4; ++pp) {
                const ull f = fdup[pr + 16 * pp][i];
                acc[pp][0] = fma2(f, w01.x, acc[pp][0]);
                acc[pp][1] = fma2(f, w01.y, acc[pp][1]);
            }
        }

        #pragma unroll
        for (int pp = 0; pp < 4; ++pp) {
            const int n = base + pr + 16 * pp;
            if (n < NPTS) {
                *(ull*)&out[n * 64 + 4 * c4]     = acc[pp][0];
                *(ull*)&out[n * 64 + 4 * c4 + 2] = acc[pp][1];
            }
        }
        __syncthreads();
    }
}

// ============================================================================
extern "C" void kernel_launch(void* const* d_in, const int* in_sizes, int n_in,
                              void* d_out, int out_size) {
    const float* feats = (const float*)d_in[0];
    const int*   knn   = (const int*)  d_in[1];
    const float* Wq    = (const float*)d_in[2];
    const float* Wk    = (const float*)d_in[3];
    const float* Wv    = (const float*)d_in[4];
    const float* Wo    = (const float*)d_in[5];
    const float* bo    = (const float*)d_in[6];
    float* out = (float*)d_out;

    proj_qkv_kernel<<<296, 256>>>(feats, Wq, Wk, Wv);   // 2 blocks/SM, persistent
    attn_kernel<<<12500, 256>>>(knn);
    out_proj_kernel<<<592, 256>>>(Wo, bo, out);          // 4 blocks/SM, persistent
}